// round 11
// baseline (speedup 1.0000x reference)
#include <cuda_runtime.h>
#include <math.h>

#define NCLS 1000
#define NV4  250   // 1000 floats = 250 float4 per row

// Monotone float -> u32 map (order-preserving; 0 is the bottom identity)
__device__ __forceinline__ unsigned fmap(float x) {
    int i = __float_as_int(x);
    return (i < 0) ? ~(unsigned)i : ((unsigned)i | 0x80000000u);
}
__device__ __forceinline__ float funmap(unsigned u) {
    int i = (u & 0x80000000u) ? (int)(u & 0x7FFFFFFFu) : ~(int)u;
    return __int_as_float(i);
}

// Self-resetting cross-launch scratch (zero at load; last block re-zeros)
__device__ unsigned g_gmax  = 0;
__device__ unsigned g_count = 0;

__global__ __launch_bounds__(512, 4) void margin_kernel(
    const float* __restrict__ o1, const float* __restrict__ o2,
    const float* __restrict__ o3, const float* __restrict__ o4,
    const float* __restrict__ mim, const int* __restrict__ targets,
    float* __restrict__ out_max, float* __restrict__ out_thr)
{
    const int tid   = threadIdx.x;
    const int half  = tid >> 8;            // 0: row A, 1: row B
    const int htid  = tid & 255;           // thread id within the half
    const int row   = blockIdx.x * 2 + half;

    const float* mats[5] = {o1, o2, o3, o4, mim};

    __shared__ float    s_tgt[2][5];
    __shared__ unsigned s_red[2][5][8];
    __shared__ float    s_g[2];

    const int t    = targets[row];         // int32
    const int town = t >> 2, tsub = t & 3;

    // ---- load phase: 5 independent streaming float4 loads per thread ----
    float4 v[5];
    const bool active = (htid < NV4);
    if (active) {
        const size_t base = (size_t)row * NCLS;
        #pragma unroll
        for (int m = 0; m < 5; m++)
            v[m] = __ldcs(reinterpret_cast<const float4*>(mats[m] + base) + htid);
    }

    // ---- per-thread max (excluding target element) + target capture ----
    unsigned u[5];
    const bool own = (htid == town);
    #pragma unroll
    for (int m = 0; m < 5; m++) {
        float a = -INFINITY, b = -INFINITY, c = -INFINITY, d = -INFINITY;
        if (active) { a = v[m].x; b = v[m].y; c = v[m].z; d = v[m].w; }
        float mx = fmaxf(fmaxf(a, b), fmaxf(c, d));
        if (own) {   // one thread per row: capture tgt value, exclude it
            float tv = (tsub == 0) ? a : (tsub == 1) ? b : (tsub == 2) ? c : d;
            s_tgt[half][m] = tv;
            float ea = (tsub == 0) ? -INFINITY : a;
            float eb = (tsub == 1) ? -INFINITY : b;
            float ec = (tsub == 2) ? -INFINITY : c;
            float ed = (tsub == 3) ? -INFINITY : d;
            mx = fmaxf(fmaxf(ea, eb), fmaxf(ec, ed));
        }
        u[m] = fmap(mx);
    }

    // ---- warp reduction: single REDUX per matrix ----
    #pragma unroll
    for (int m = 0; m < 5; m++)
        u[m] = __reduce_max_sync(0xFFFFFFFFu, u[m]);

    const int hwarp = htid >> 5, lane = tid & 31;
    if (lane == 0) {
        #pragma unroll
        for (int m = 0; m < 5; m++) s_red[half][m][hwarp] = u[m];
    }
    __syncthreads();

    // ---- per-row epilogue: thread 0 of each half finishes its row ----
    if (htid == 0) {
        float m_excl[5];
        #pragma unroll
        for (int m = 0; m < 5; m++) {
            unsigned um = s_red[half][m][0];
            #pragma unroll
            for (int w = 1; w < 8; w++) um = max(um, s_red[half][m][w]);
            m_excl[m] = funmap(um);
        }

        // row max over mats 0..3 (restore excluded target element)
        float g = -INFINITY;
        #pragma unroll
        for (int m = 0; m < 4; m++) g = fmaxf(g, fmaxf(m_excl[m], s_tgt[half][m]));
        s_g[half] = g;

        // margin = max(0, tgt - max_excl), /TEMPERATURE(=2) folded in
        float margin[5];
        #pragma unroll
        for (int m = 0; m < 5; m++)
            margin[m] = fmaxf(0.0f, (s_tgt[half][m] - m_excl[m]) * 0.5f);

        float mx = margin[0];
        #pragma unroll
        for (int m = 1; m < 5; m++) mx = fmaxf(mx, margin[m]);
        float e[5], s = 0.0f;
        #pragma unroll
        for (int m = 0; m < 5; m++) { e[m] = __expf(margin[m] - mx); s += e[m]; }
        float inv = 1.0f / s;
        float* dst = out_thr + (size_t)row * 5;
        #pragma unroll
        for (int m = 0; m < 5; m++) dst[m] = e[m] * inv;
    }
    __syncthreads();

    // ---- one atomic pair per block; last block publishes + resets ----
    if (tid == 0) {
        float gblk = fmaxf(s_g[0], s_g[1]);
        atomicMax(&g_gmax, fmap(gblk));
        __threadfence();
        unsigned c = atomicAdd(&g_count, 1);
        if (c == gridDim.x - 1) {
            unsigned final_u = atomicMax(&g_gmax, 0u);
            *out_max = funmap(final_u);
            atomicExch(&g_gmax, 0u);
            atomicExch(&g_count, 0u);
        }
    }
}

extern "C" void kernel_launch(void* const* d_in, const int* in_sizes, int n_in,
                              void* d_out, int out_size)
{
    const float* o1  = (const float*)d_in[0];
    const float* o2  = (const float*)d_in[1];
    const float* o3  = (const float*)d_in[2];
    const float* o4  = (const float*)d_in[3];
    const float* mim = (const float*)d_in[4];
    const int*   tgt = (const int*)d_in[5];

    const int n = in_sizes[5];          // 16384 rows (even)
    float* out = (float*)d_out;

    float* out_thr = out + ((size_t)out_size - (size_t)n * 5);
    float* out_max = out;

    margin_kernel<<<n / 2, 512>>>(o1, o2, o3, o4, mim, tgt, out_max, out_thr);
}